// round 14
// baseline (speedup 1.0000x reference)
#include <cuda_runtime.h>
#include <cuda_bf16.h>
#include <math.h>
#include <stdint.h>

#define NN 20000
#define EE 320000
#define DD 256
#define HH 2
#define CC 128
#define LL 3
#define EK 96      // edge-attr dim padded (real 73)

// ---------------- scratch (static __device__, no allocation) ----------------
__device__ float g_ea[EE * EK];                    // fp32 edge attrs (123 MB)
__device__ __nv_bfloat16 g_h_hi[NN * 256];
__device__ __nv_bfloat16 g_h_lo[NN * 256];
__device__ __nv_bfloat16 g_x_hi[NN * 128];
__device__ __nv_bfloat16 g_x_lo[NN * 128];
__device__ __nv_bfloat16 g_wn_hi[3 * 1280 * 256];  // per layer rows: Wq|Wk|Wv|Ws|Wc (K-major)
__device__ __nv_bfloat16 g_wn_lo[3 * 1280 * 256];
__device__ __nv_bfloat16 g_wl_hi[256 * 128];
__device__ __nv_bfloat16 g_wl_lo[256 * 128];
__device__ float g_wef[3 * EK * 256];              // fp32 We, [layer][d][c] (zero-padded d>=73)
__device__ float g_asum[HH * NN * EK];             // softmax-weighted edge-attr sums (fp32)
__device__ float g_bz[3 * 256];                    // bias of z block

__device__ float g_h[NN * DD];
__device__ float g_q[NN * DD];
__device__ float g_k[NN * DD];
__device__ float g_v[NN * DD];
__device__ float g_skip[NN * DD];
__device__ float g_z[NN * DD];                     // z = We^T q, per head 128-col block
__device__ float g_aggr[NN * DD];
__device__ int   g_rowptr[NN + 1];
__device__ int   g_cursor[NN];
__device__ int   g_deg[NN];
__device__ int2  g_edge[EE];                       // (eid, src)

__device__ __forceinline__ uint32_t smem_u32(const void* p) {
    uint32_t a;
    asm("{ .reg .u64 t; cvta.to.shared.u64 t, %1; cvt.u32.u64 %0, t; }" : "=r"(a) : "l"(p));
    return a;
}
__device__ __forceinline__ void splitbf(float x, __nv_bfloat16& h, __nv_bfloat16& l) {
    h = __float2bfloat16(x);
    l = __float2bfloat16(x - __bfloat162float(h));
}

// ---------------- CSR build ----------------
__global__ void k_zero_deg() {
    int i = blockIdx.x * blockDim.x + threadIdx.x;
    if (i < NN) g_deg[i] = 0;
}
__global__ void k_count(const int* __restrict__ ei) {
    int e = blockIdx.x * blockDim.x + threadIdx.x;
    if (e < EE) atomicAdd(&g_deg[ei[EE + e]], 1);
}
__global__ void k_scan() {
    __shared__ int sums[1024];
    const int PER = 20;
    int tid = threadIdx.x;
    int base = tid * PER;
    int local[PER];
    int s = 0;
#pragma unroll
    for (int i = 0; i < PER; i++) {
        int idx = base + i;
        int d = (idx < NN) ? g_deg[idx] : 0;
        local[i] = s;
        s += d;
    }
    sums[tid] = s;
    __syncthreads();
    for (int off = 1; off < 1024; off <<= 1) {
        int t2 = (tid >= off) ? sums[tid - off] : 0;
        __syncthreads();
        sums[tid] += t2;
        __syncthreads();
    }
    int pre = (tid > 0) ? sums[tid - 1] : 0;
#pragma unroll
    for (int i = 0; i < PER; i++) {
        int idx = base + i;
        if (idx < NN) {
            g_rowptr[idx] = pre + local[i];
            g_cursor[idx] = 0;
        }
    }
    if (tid == 1023) g_rowptr[NN] = sums[1023];
}
__global__ void k_scatter(const int* __restrict__ ei) {
    int e = blockIdx.x * blockDim.x + threadIdx.x;
    if (e < EE) {
        int d = ei[EE + e];
        int pos = g_rowptr[d] + atomicAdd(&g_cursor[d], 1);
        g_edge[pos] = make_int2(e, ei[e]);
    }
}

// ---------------- edge attributes (fp32, zero pad to 96) ----------------
__global__ void k_edge_attr(const int* __restrict__ ei,
                            const float* __restrict__ last_update,
                            const float* __restrict__ t,
                            const float* __restrict__ msg,
                            const float* __restrict__ wlin,
                            const float* __restrict__ blin,
                            const float* __restrict__ w,
                            const float* __restrict__ b) {
    int idx = blockIdx.x * blockDim.x + threadIdx.x;
    if (idx >= EE * EK) return;
    int e = idx / EK;
    int j = idx - e * EK;
    float v;
    if (j < 9) {
        float rel = last_update[ei[e]] - t[e];
        if (j == 0) v = rel * wlin[0] + blin[0];
        else        v = sinf(rel * w[j - 1] + b[j - 1]);
    } else if (j < 73) {
        v = msg[e * 64 + (j - 9)];
    } else {
        v = 0.f;
    }
    g_ea[idx] = v;
}

// ---------------- weight packing ----------------
__global__ void k_split_wn(const float* __restrict__ Wq, const float* __restrict__ Wk,
                           const float* __restrict__ Wv, const float* __restrict__ Ws) {
    int idx = blockIdx.x * blockDim.x + threadIdx.x;
    if (idx >= 12 * 65536) return;
    int mat = idx >> 16;
    int r = idx & 65535;
    int n = r >> 8, k = r & 255;
    int layer = mat >> 2, ty = mat & 3;
    const float* W = (ty == 0 ? Wq : ty == 1 ? Wk : ty == 2 ? Wv : Ws) + layer * 65536;
    int dst = layer * 1280 * 256 + (ty * 256 + n) * 256 + k;
    splitbf(W[k * 256 + n], g_wn_hi[dst], g_wn_lo[dst]);
}
// composite Wc rows (1024..1279): Wc[k][c=h*128+j] = sum_m Wq[k][h*128+m]*We[j][h*128+m]
__global__ void k_wc(const float* __restrict__ Wq, const float* __restrict__ We) {
    int idx = blockIdx.x * blockDim.x + threadIdx.x;
    if (idx >= 3 * 65536) return;
    int layer = idx >> 16;
    int o = idx & 65535;
    int c = o >> 8, k = o & 255;
    int hh = c >> 7, j = c & 127;
    float s = 0.f;
    if (j < 73) {
        const float* wq = Wq + layer * 65536 + k * 256 + hh * 128;
        const float* we = We + layer * 73 * 256 + j * 256 + hh * 128;
#pragma unroll 8
        for (int m = 0; m < 128; m++) s += wq[m] * we[m];
    }
    int dst = layer * 1280 * 256 + (1024 + c) * 256 + k;
    splitbf(s, g_wn_hi[dst], g_wn_lo[dst]);
}
__global__ void k_bz(const float* __restrict__ bq, const float* __restrict__ We) {
    int idx = blockIdx.x * blockDim.x + threadIdx.x;
    if (idx >= 3 * 256) return;
    int layer = idx >> 8, c = idx & 255;
    int hh = c >> 7, j = c & 127;
    float s = 0.f;
    if (j < 73) {
        const float* bqp = bq + layer * 256 + hh * 128;
        const float* we = We + layer * 73 * 256 + j * 256 + hh * 128;
#pragma unroll 8
        for (int m = 0; m < 128; m++) s += bqp[m] * we[m];
    }
    g_bz[idx] = s;
}
__global__ void k_wef(const float* __restrict__ We) {
    int idx = blockIdx.x * blockDim.x + threadIdx.x;
    if (idx >= 3 * EK * 256) return;
    int l = idx / (EK * 256);
    int r = idx - l * (EK * 256);
    int d = r >> 8, c = r & 255;
    g_wef[idx] = (d < 73) ? We[l * 73 * 256 + d * 256 + c] : 0.f;
}
__global__ void k_split_wl(const float* __restrict__ lin_w) {
    int idx = blockIdx.x * blockDim.x + threadIdx.x;
    if (idx >= 32768) return;
    int n = idx >> 7, k = idx & 127;
    float v = (k < 100) ? lin_w[k * 256 + n] : 0.f;
    splitbf(v, g_wl_hi[idx], g_wl_lo[idx]);
}
__global__ void k_split_x(const float* __restrict__ x) {
    int idx = blockIdx.x * blockDim.x + threadIdx.x;
    if (idx >= NN * 128) return;
    int m = idx >> 7, k = idx & 127;
    float v = (k < 100) ? x[m * 100 + k] : 0.f;
    splitbf(v, g_x_hi[idx], g_x_lo[idx]);
}
__global__ void k_split_h() {
    int idx = blockIdx.x * blockDim.x + threadIdx.x;
    if (idx >= NN * 256) return;
    splitbf(g_h[idx], g_h_hi[idx], g_h_lo[idx]);
}

// ---------------- split-bf16 mma.sync GEMM, K-tile 64, 5 output blocks ----------------
#define LDT 72                        // smem row stride in bf16 (144 B)
#define TILE_B (128 * LDT * 2)        // 18432 B per operand tile
#define STAGE_B (4 * TILE_B)          // 73728
#define SMEM_MM (2 * STAGE_B)         // 147456 B

__device__ __forceinline__ void mma16816(float* d, const uint32_t* a, const uint32_t* b) {
    asm volatile(
        "mma.sync.aligned.m16n8k16.row.col.f32.bf16.bf16.f32 "
        "{%0,%1,%2,%3},{%4,%5,%6,%7},{%8,%9},{%0,%1,%2,%3};"
        : "+f"(d[0]), "+f"(d[1]), "+f"(d[2]), "+f"(d[3])
        : "r"(a[0]), "r"(a[1]), "r"(a[2]), "r"(a[3]), "r"(b[0]), "r"(b[1]));
}
__device__ __forceinline__ void ldm4(uint32_t* r, uint32_t addr) {
    asm volatile("ldmatrix.sync.aligned.m8n8.x4.shared.b16 {%0,%1,%2,%3}, [%4];"
                 : "=r"(r[0]), "=r"(r[1]), "=r"(r[2]), "=r"(r[3]) : "r"(addr));
}
__device__ __forceinline__ void cp16(uint32_t dst, const void* src, int szr) {
    asm volatile("cp.async.cg.shared.global [%0], [%1], 16, %2;"
                 :: "r"(dst), "l"(src), "r"(szr));
}

__device__ __forceinline__ void mm_load_stage(
    uint32_t sbase, int st, int kt, int row0, int col0, int M, int K,
    const __nv_bfloat16* Ah, const __nv_bfloat16* Al,
    const __nv_bfloat16* Bh, const __nv_bfloat16* Bl, int tid) {
    int kg0 = kt * 64;
#pragma unroll
    for (int i = 0; i < 16; i++) {
        int c = tid + i * 256;                 // 0..4095
        int op = c >> 10;                      // 0:Ah 1:Al 2:Bh 3:Bl
        int r = (c >> 3) & 127, seg = c & 7;
        const __nv_bfloat16* S = (op == 0) ? Ah : (op == 1) ? Al : (op == 2) ? Bh : Bl;
        int gr = (op < 2) ? (row0 + r) : (col0 + r);
        int valid = (op < 2) ? (gr < M) : 1;
        uint32_t dst = sbase + st * STAGE_B + op * TILE_B + r * (LDT * 2) + seg * 16;
        const __nv_bfloat16* src = S + (valid ? ((size_t)gr * K + kg0 + seg * 8) : 0);
        cp16(dst, src, valid ? 16 : 0);
    }
}

__global__ __launch_bounds__(256) void k_mma(
    const __nv_bfloat16* __restrict__ Ah, const __nv_bfloat16* __restrict__ Al,
    const __nv_bfloat16* __restrict__ Bh, const __nv_bfloat16* __restrict__ Bl,
    const float* b0, const float* b1, const float* b2, const float* b3, const float* b4,
    float* C0, float* C1, float* C2, float* C3, float* C4,
    int M, int K) {
    extern __shared__ char sm[];
    uint32_t sbase = smem_u32(sm);
    int tid = threadIdx.x, warp = tid >> 5, lane = tid & 31;
    int g = lane >> 2, tig = lane & 3;
    int wm = (warp & 1) * 64, wn = (warp >> 1) * 32;
    int row0 = blockIdx.y * 128, col0 = blockIdx.x * 128;
    int nkt = K >> 6;

    float acc[4][4][4];
#pragma unroll
    for (int mi = 0; mi < 4; mi++)
#pragma unroll
        for (int ni = 0; ni < 4; ni++)
#pragma unroll
            for (int r = 0; r < 4; r++) acc[mi][ni][r] = 0.f;

    mm_load_stage(sbase, 0, 0, row0, col0, M, K, Ah, Al, Bh, Bl, tid);
    asm volatile("cp.async.commit_group;");

    for (int kt = 0; kt < nkt; kt++) {
        if (kt + 1 < nkt) {
            mm_load_stage(sbase, (kt + 1) & 1, kt + 1, row0, col0, M, K, Ah, Al, Bh, Bl, tid);
            asm volatile("cp.async.commit_group;");
            asm volatile("cp.async.wait_group 1;");
        } else {
            asm volatile("cp.async.wait_group 0;");
        }
        __syncthreads();

        uint32_t at  = sbase + (kt & 1) * STAGE_B;
        uint32_t alt = at + TILE_B;
        uint32_t bt  = at + 2 * TILE_B;
        uint32_t blt = at + 3 * TILE_B;
        int arow = (lane & 15);
        int acol = (lane >> 4) * 8;
#pragma unroll
        for (int ks = 0; ks < 64; ks += 16) {
            uint32_t rah[4][4], ral[4][4], rbh[4][2], rbl[4][2];
#pragma unroll
            for (int mi = 0; mi < 4; mi++) {
                uint32_t off = ((wm + mi * 16 + arow) * LDT + ks + acol) * 2;
                ldm4(rah[mi], at + off);
                ldm4(ral[mi], alt + off);
            }
#pragma unroll
            for (int ni = 0; ni < 4; ni++) {
                uint32_t off = ((wn + ni * 8 + g) * LDT + ks + 2 * tig) * 2;
                rbh[ni][0] = *(const uint32_t*)(sm + (bt - sbase) + off);
                rbh[ni][1] = *(const uint32_t*)(sm + (bt - sbase) + off + 16);
                rbl[ni][0] = *(const uint32_t*)(sm + (blt - sbase) + off);
                rbl[ni][1] = *(const uint32_t*)(sm + (blt - sbase) + off + 16);
            }
#pragma unroll
            for (int mi = 0; mi < 4; mi++)
#pragma unroll
                for (int ni = 0; ni < 4; ni++) {
                    mma16816(acc[mi][ni], rah[mi], rbh[ni]);
                    mma16816(acc[mi][ni], rah[mi], rbl[ni]);
                    mma16816(acc[mi][ni], ral[mi], rbh[ni]);
                }
        }
        __syncthreads();
    }

    int cb = col0 >> 8;
    float* C = (cb == 0) ? C0 : (cb == 1) ? C1 : (cb == 2) ? C2 : (cb == 3) ? C3 : C4;
    const float* bias = (cb == 0) ? b0 : (cb == 1) ? b1 : (cb == 2) ? b2 : (cb == 3) ? b3 : b4;
    int coll0 = col0 & 255;
#pragma unroll
    for (int ni = 0; ni < 4; ni++) {
        int col = coll0 + wn + ni * 8 + 2 * tig;
        float2 bz = make_float2(0.f, 0.f);
        if (bias) bz = *(const float2*)(bias + col);
#pragma unroll
        for (int mi = 0; mi < 4; mi++) {
            int r = row0 + wm + mi * 16 + g;
            if (r < M) {
                float2 o = make_float2(acc[mi][ni][0] + bz.x, acc[mi][ni][1] + bz.y);
                *(float2*)(C + (size_t)r * 256 + col) = o;
            }
            if (r + 8 < M) {
                float2 o = make_float2(acc[mi][ni][2] + bz.x, acc[mi][ni][3] + bz.y);
                *(float2*)(C + (size_t)(r + 8) * 256 + col) = o;
            }
        }
    }
}

// ---------------- attention: ONE warp per node, both heads ----------------
// lane owns 8 channels of the 256-dim row: lanes 0-15 = head0, 16-31 = head1.
// alpha_h = scale * (q_h·k_h[src] + z_h·ea);  aggr = sum softmax(alpha)*v; asum = sum a*ea.
__global__ void k_attn() {
    int n = (blockIdx.x * blockDim.x + threadIdx.x) >> 5;
    int lane = threadIdx.x & 31;
    if (n >= NN) return;
    int c0 = lane * 8;
    int base = n * DD + c0;
    const float4 qa = *(const float4*)(g_q + base);
    const float4 qb = *(const float4*)(g_q + base + 4);
    bool eal = (lane < 24);
    float4 z0 = make_float4(0.f, 0.f, 0.f, 0.f), z1 = z0;
    if (eal) {
        z0 = *(const float4*)(g_z + n * DD + lane * 4);
        z1 = *(const float4*)(g_z + n * DD + 128 + lane * 4);
    }
    int hsel = lane >> 4;
    int beg = g_rowptr[n], end = g_rowptr[n + 1];
    float m0 = -3.4e38f, l0 = 0.f, m1 = -3.4e38f, l1 = 0.f;
    float4 aca = make_float4(0.f, 0.f, 0.f, 0.f), acb = aca;
    float4 s0 = aca, s1 = aca;
    const float scale = 0.0883883476483184406f;  // 1/sqrt(128)

    int i = beg;
    for (; i + 2 <= end; i += 2) {
        int2 edA = g_edge[i];
        int2 edB = g_edge[i + 1];
        float4 eaA = make_float4(0.f, 0.f, 0.f, 0.f), eaB = eaA;
        if (eal) {
            eaA = *(const float4*)(g_ea + (size_t)edA.x * EK + lane * 4);
            eaB = *(const float4*)(g_ea + (size_t)edB.x * EK + lane * 4);
        }
        size_t sA = (size_t)edA.y * DD + c0, sB = (size_t)edB.y * DD + c0;
        const float4 kAa = *(const float4*)(g_k + sA);
        const float4 kAb = *(const float4*)(g_k + sA + 4);
        const float4 kBa = *(const float4*)(g_k + sB);
        const float4 kBb = *(const float4*)(g_k + sB + 4);
        const float4 vAa = *(const float4*)(g_v + sA);
        const float4 vAb = *(const float4*)(g_v + sA + 4);
        const float4 vBa = *(const float4*)(g_v + sB);
        const float4 vBb = *(const float4*)(g_v + sB + 4);
        float pkA = qa.x * kAa.x + qa.y * kAa.y + qa.z * kAa.z + qa.w * kAa.w +
                    qb.x * kAb.x + qb.y * kAb.y + qb.z * kAb.z + qb.w * kAb.w;
        float pkB = qa.x * kBa.x + qa.y * kBa.y + qa.z * kBa.z + qa.w * kBa.w +
                    qb.x * kBb.x + qb.y * kBb.y + qb.z * kBb.z + qb.w * kBb.w;
        float peA0 = z0.x * eaA.x + z0.y * eaA.y + z0.z * eaA.z + z0.w * eaA.w;
        float peA1 = z1.x * eaA.x + z1.y * eaA.y + z1.z * eaA.z + z1.w * eaA.w;
        float peB0 = z0.x * eaB.x + z0.y * eaB.y + z0.z * eaB.z + z0.w * eaB.w;
        float peB1 = z1.x * eaB.x + z1.y * eaB.y + z1.z * eaB.z + z1.w * eaB.w;
        float rA0 = (hsel == 0 ? pkA : 0.f) + peA0;
        float rA1 = (hsel != 0 ? pkA : 0.f) + peA1;
        float rB0 = (hsel == 0 ? pkB : 0.f) + peB0;
        float rB1 = (hsel != 0 ? pkB : 0.f) + peB1;
#pragma unroll
        for (int off = 16; off; off >>= 1) {
            rA0 += __shfl_xor_sync(0xffffffffu, rA0, off);
            rA1 += __shfl_xor_sync(0xffffffffu, rA1, off);
            rB0 += __shfl_xor_sync(0xffffffffu, rB0, off);
            rB1 += __shfl_xor_sync(0xffffffffu, rB1, off);
        }
        float aA0 = rA0 * scale, aA1 = rA1 * scale;
        float aB0 = rB0 * scale, aB1 = rB1 * scale;
        float m0n = fmaxf(m0, fmaxf(aA0, aB0));
        float m1n = fmaxf(m1, fmaxf(aA1, aB1));
        float c0f = __expf(m0 - m0n), c1f = __expf(m1 - m1n);
        float wA0 = __expf(aA0 - m0n), wB0 = __expf(aB0 - m0n);
        float wA1 = __expf(aA1 - m1n), wB1 = __expf(aB1 - m1n);
        l0 = l0 * c0f + wA0 + wB0;
        l1 = l1 * c1f + wA1 + wB1;
        float csel = hsel ? c1f : c0f;
        float wAs = hsel ? wA1 : wA0;
        float wBs = hsel ? wB1 : wB0;
        aca.x = aca.x * csel + wAs * vAa.x + wBs * vBa.x;
        aca.y = aca.y * csel + wAs * vAa.y + wBs * vBa.y;
        aca.z = aca.z * csel + wAs * vAa.z + wBs * vBa.z;
        aca.w = aca.w * csel + wAs * vAa.w + wBs * vBa.w;
        acb.x = acb.x * csel + wAs * vAb.x + wBs * vBb.x;
        acb.y = acb.y * csel + wAs * vAb.y + wBs * vBb.y;
        acb.z = acb.z * csel + wAs * vAb.z + wBs * vBb.z;
        acb.w = acb.w * csel + wAs * vAb.w + wBs * vBb.w;
        s0.x = s0.x * c0f + wA0 * eaA.x + wB0 * eaB.x;
        s0.y = s0.y * c0f + wA0 * eaA.y + wB0 * eaB.y;
        s0.z = s0.z * c0f + wA0 * eaA.z + wB0 * eaB.z;
        s0.w = s0.w * c0f + wA0 * eaA.w + wB0 * eaB.w;
        s1.x = s1.x * c1f + wA1 * eaA.x + wB1 * eaB.x;
        s1.y = s1.y * c1f + wA1 * eaA.y + wB1 * eaB.y;
        s1.z = s1.z * c1f + wA1 * eaA.z + wB1 * eaB.z;
        s1.w = s1.w * c1f + wA1 * eaA.w + wB1 * eaB.w;
        m0 = m0n; m1 = m1n;
    }
    for (; i < end; i++) {
        int2 ed = g_edge[i];
        float4 eaA = make_float4(0.f, 0.f, 0.f, 0.f);
        if (eal) eaA = *(const float4*)(g_ea + (size_t)ed.x * EK + lane * 4);
        size_t sA = (size_t)ed.y * DD + c0;
        const float4 kAa = *(const float4*)(g_k + sA);
        const float4 kAb = *(const float4*)(g_k + sA + 4);
        const float4 vAa = *(const float4*)(g_v + sA);
        const float4 vAb = *(const float4*)(g_v + sA + 4);
        float pkA = qa.x * kAa.x + qa.y * kAa.y + qa.z * kAa.z + qa.w * kAa.w +
                    qb.x * kAb.x + qb.y * kAb.y + qb.z * kAb.z + qb.w * kAb.w;
        float peA0 = z0.x * eaA.x + z0.y * eaA.y + z0.z * eaA.z + z0.w * eaA.w;
        float peA1 = z1.x * eaA.x + z1.y * eaA.y + z1.z * eaA.z + z1.w * eaA.w;
        float rA0 = (hsel == 0 ? pkA : 0.f) + peA0;
        float rA1 = (hsel != 0 ? pkA : 0.f) + peA1;
#pragma unroll
        for (int off = 16; off; off >>= 1) {
            rA0 += __shfl_xor_sync(0xffffffffu, rA0, off);
            rA1 += __shfl_xor_sync(0xffffffffu, rA1, off);
        }
        float aA0 = rA0 * scale, aA1 = rA1 * scale;
        float m0n = fmaxf(m0, aA0), m1n = fmaxf(m1, aA1);
        float c0f = __expf(m0 - m0n), c1f = __expf(m1 - m1n);
        float wA0 = __expf(aA0 - m0n), wA1 = __expf(aA1 - m1n);
        l0 = l0 * c0f + wA0;
        l1 = l1 * c1f + wA1;
        float csel = hsel ? c1f : c0f;
        float wAs = hsel ? wA1 : wA0;
        aca.x = aca.x * csel + wAs * vAa.x;
        aca.y = aca.y * csel + wAs * vAa.y;
        aca.z = aca.z * csel + wAs * vAa.z;
        aca.w = aca.w * csel + wAs * vAa.w;
        acb.x = acb.x * csel + wAs * vAb.x;
        acb.y = acb.y * csel + wAs * vAb.y;
        acb.z = acb.z * csel + wAs * vAb.z;
        acb.w = acb.w * csel + wAs * vAb.w;
        s0.x = s0.x * c0f + wA0 * eaA.x;
        s0.y = s0.y * c0f + wA0 * eaA.y;
        s0.z = s0.z * c0f + wA0 * eaA.z;
        s0.w = s0.w * c0f + wA0 * eaA.w;
        s1.x = s1.x * c1f + wA1 * eaA.x;
        s1.y = s1.y * c1f + wA1 * eaA.y;
        s1.z = s1.z * c1f + wA1 * eaA.z;
        s1.w = s1.w * c1f + wA1 * eaA.w;
        m0 = m0n; m1 = m1n;
    }
    float inv0 = (l0 > 0.f) ? 1.f / l0 : 0.f;
    float inv1 = (l1 > 0.f) ? 1.f / l1 : 0.f;
    float invsel = hsel ? inv1 : inv0;
    float4 oa = make_float4(aca.x * invsel, aca.y * invsel, aca.z * invsel, aca.w * invsel);
    float4 ob = make_float4(acb.x * invsel, acb.y * invsel, acb.z * invsel, acb.w * invsel);
    *(float4*)(g_aggr + base) = oa;
    *(float4*)(g_aggr + base + 4) = ob;
    if (eal) {
        float4 w0 = make_float4(s0.x * inv0, s0.y * inv0, s0.z * inv0, s0.w * inv0);
        float4 w1 = make_float4(s1.x * inv1, s1.y * inv1, s1.z * inv1, s1.w * inv1);
        *(float4*)(g_asum + (size_t)n * EK + lane * 4) = w0;
        *(float4*)(g_asum + (size_t)(NN + n) * EK + lane * 4) = w1;
    }
}

// ---------------- residual + e-contribution + layernorm + silu (+ fused split) ----------------
__global__ void k_node_update(const float* __restrict__ ln_g,
                              const float* __restrict__ ln_b,
                              const float* __restrict__ wef,
                              float* __restrict__ out) {
    __shared__ float sas[2 * EK];
    __shared__ float red[8];
    int n = blockIdx.x, t = threadIdx.x;
    int idx = n * DD + t;
    if (t < EK)            sas[t] = g_asum[(size_t)n * EK + t];
    else if (t < 2 * EK)   sas[t] = g_asum[(size_t)(NN + n) * EK + (t - EK)];
    __syncthreads();

    // e-contribution for channel t: sum_d asum[head(t)][d] * We[d][t]
    const float* sp = sas + (t >> 7) * EK;
    const float* wcol = wef + t;
    float ag2 = 0.f;
#pragma unroll 8
    for (int d = 0; d < EK; d++) ag2 += sp[d] * wcol[d * 256];

    float y = g_h[idx] + g_aggr[idx] + ag2 + g_skip[idx];
    int w = t >> 5, lane = t & 31;

    float s = y;
#pragma unroll
    for (int off = 16; off; off >>= 1) s += __shfl_xor_sync(0xffffffffu, s, off);
    if (lane == 0) red[w] = s;
    __syncthreads();
    float mu = 0.f;
#pragma unroll
    for (int i = 0; i < 8; i++) mu += red[i];
    mu *= (1.f / DD);

    float d = y - mu;
    float s2 = d * d;
#pragma unroll
    for (int off = 16; off; off >>= 1) s2 += __shfl_xor_sync(0xffffffffu, s2, off);
    __syncthreads();
    if (lane == 0) red[w] = s2;
    __syncthreads();
    float var = 0.f;
#pragma unroll
    for (int i = 0; i < 8; i++) var += red[i];
    var *= (1.f / DD);

    float z = d * rsqrtf(var + 1e-5f) * ln_g[t] + ln_b[t];
    float y2 = z / (1.f + __expf(-z));
    out[idx] = y2;
    splitbf(y2, g_h_hi[idx], g_h_lo[idx]);
}

// ---------------- launch ----------------
extern "C" void kernel_launch(void* const* d_in, const int* in_sizes, int n_in,
                              void* d_out, int out_size) {
    const float* x    = (const float*)d_in[0];
    const float* lu   = (const float*)d_in[1];
    const int*   ei   = (const int*)d_in[2];
    const float* t    = (const float*)d_in[3];
    const float* msg  = (const float*)d_in[4];
    const float* wlin = (const float*)d_in[5];
    const float* blin = (const float*)d_in[6];
    const float* w    = (const float*)d_in[7];
    const float* b    = (const float*)d_in[8];
    const float* lin_w = (const float*)d_in[9];
    const float* lin_b = (const float*)d_in[10];
    const float* Wq = (const float*)d_in[11];
    const float* bq = (const float*)d_in[12];
    const float* Wk = (const float*)d_in[13];
    const float* bk = (const float*)d_in[14];
    const float* Wv = (const float*)d_in[15];
    const float* bv = (const float*)d_in[16];
    const float* We = (const float*)d_in[17];
    const float* Ws = (const float*)d_in[18];
    const float* bs = (const float*)d_in[19];
    const float* lng = (const float*)d_in[20];
    const float* lnb = (const float*)d_in[21];
    float* out = (float*)d_out;

    cudaFuncSetAttribute(k_mma, cudaFuncAttributeMaxDynamicSharedMemorySize, SMEM_MM);

    void* p;
    cudaGetSymbolAddress(&p, g_h);    float* ph = (float*)p;
    cudaGetSymbolAddress(&p, g_q);    float* pq = (float*)p;
    cudaGetSymbolAddress(&p, g_k);    float* pk = (float*)p;
    cudaGetSymbolAddress(&p, g_v);    float* pv = (float*)p;
    cudaGetSymbolAddress(&p, g_skip); float* ps = (float*)p;
    cudaGetSymbolAddress(&p, g_z);    float* pz = (float*)p;
    cudaGetSymbolAddress(&p, g_bz);   float* pbz = (float*)p;
    cudaGetSymbolAddress(&p, g_wef);  float* pwef = (float*)p;
    cudaGetSymbolAddress(&p, g_h_hi);  __nv_bfloat16* hhi = (__nv_bfloat16*)p;
    cudaGetSymbolAddress(&p, g_h_lo);  __nv_bfloat16* hlo = (__nv_bfloat16*)p;
    cudaGetSymbolAddress(&p, g_x_hi);  __nv_bfloat16* xhi = (__nv_bfloat16*)p;
    cudaGetSymbolAddress(&p, g_x_lo);  __nv_bfloat16* xlo = (__nv_bfloat16*)p;
    cudaGetSymbolAddress(&p, g_wn_hi); __nv_bfloat16* wnh = (__nv_bfloat16*)p;
    cudaGetSymbolAddress(&p, g_wn_lo); __nv_bfloat16* wnl = (__nv_bfloat16*)p;
    cudaGetSymbolAddress(&p, g_wl_hi); __nv_bfloat16* wlh = (__nv_bfloat16*)p;
    cudaGetSymbolAddress(&p, g_wl_lo); __nv_bfloat16* wll = (__nv_bfloat16*)p;

    // CSR build + edge attrs + weight packing + composite z-weights
    k_zero_deg<<<(NN + 255) / 256, 256>>>();
    k_count<<<(EE + 255) / 256, 256>>>(ei);
    k_scan<<<1, 1024>>>();
    k_scatter<<<(EE + 255) / 256, 256>>>(ei);
    k_edge_attr<<<(EE * EK + 255) / 256, 256>>>(ei, lu, t, msg, wlin, blin, w, b);
    k_split_wn<<<(12 * 65536 + 255) / 256, 256>>>(Wq, Wk, Wv, Ws);
    k_wc<<<(3 * 65536 + 255) / 256, 256>>>(Wq, We);
    k_bz<<<3, 256>>>(bq, We);
    k_wef<<<(3 * EK * 256 + 255) / 256, 256>>>(We);
    k_split_wl<<<(32768 + 255) / 256, 256>>>(lin_w);
    k_split_x<<<(NN * 128 + 255) / 256, 256>>>(x);

    dim3 gin(2, (NN + 127) / 128);
    dim3 gnode(10, (NN + 127) / 128);   // Q|K|V|S|Z fused, N=1280

    k_mma<<<gin, 256, SMEM_MM>>>(xhi, xlo, wlh, wll,
                                 lin_b, lin_b, lin_b, lin_b, lin_b,
                                 ph, ph, ph, ph, ph, NN, 128);
    k_split_h<<<(NN * 256 + 255) / 256, 256>>>();

    for (int i = 0; i < LL; i++) {
        k_mma<<<gnode, 256, SMEM_MM>>>(hhi, hlo,
                                       wnh + i * 1280 * 256, wnl + i * 1280 * 256,
                                       bq + i * DD, bk + i * DD, bv + i * DD, bs + i * DD,
                                       pbz + i * 256,
                                       pq, pk, pv, ps, pz, NN, 256);
        k_attn<<<(NN * 32 + 255) / 256, 256>>>();
        k_node_update<<<NN, DD>>>(lng + i * DD, lnb + i * DD,
                                  pwef + i * EK * 256, (i == LL - 1) ? out : ph);
    }
}

// round 16
// speedup vs baseline: 1.0222x; 1.0222x over previous
#include <cuda_runtime.h>
#include <cuda_bf16.h>
#include <math.h>
#include <stdint.h>

#define NN 20000
#define EE 320000
#define DD 256
#define HH 2
#define CC 128
#define LL 3
#define EK 96      // edge-attr dim padded (real 73)

// ---------------- scratch (static __device__, no allocation) ----------------
__device__ float g_ea[EE * EK];                    // fp32 edge attrs (123 MB)
__device__ __nv_bfloat16 g_h_hi[NN * 256];
__device__ __nv_bfloat16 g_h_lo[NN * 256];
__device__ __nv_bfloat16 g_x_hi[NN * 128];
__device__ __nv_bfloat16 g_x_lo[NN * 128];
__device__ __nv_bfloat16 g_wn_hi[3 * 1280 * 256];  // per layer rows: Wq|Wk|Wv|Ws|Wc (K-major)
__device__ __nv_bfloat16 g_wn_lo[3 * 1280 * 256];
__device__ __nv_bfloat16 g_wl_hi[256 * 128];
__device__ __nv_bfloat16 g_wl_lo[256 * 128];
__device__ float g_wef[3 * EK * 256];              // fp32 We, [layer][d][c] (zero-padded d>=73)
__device__ float g_asum[HH * NN * EK];             // softmax-weighted edge-attr sums (fp32)
__device__ float g_bz[3 * 256];                    // bias of z block

__device__ float g_h[NN * DD];
__device__ float g_q[NN * DD];
__device__ float g_k[NN * DD];
__device__ float g_v[NN * DD];
__device__ float g_skip[NN * DD];
__device__ float g_z[NN * DD];                     // z = We^T q, per head 128-col block
__device__ float g_aggr[NN * DD];
__device__ int   g_rowptr[NN + 1];
__device__ int   g_cursor[NN];
__device__ int   g_deg[NN];
__device__ int2  g_edge[EE];                       // (eid, src)

__device__ __forceinline__ uint32_t smem_u32(const void* p) {
    uint32_t a;
    asm("{ .reg .u64 t; cvta.to.shared.u64 t, %1; cvt.u32.u64 %0, t; }" : "=r"(a) : "l"(p));
    return a;
}
__device__ __forceinline__ void splitbf(float x, __nv_bfloat16& h, __nv_bfloat16& l) {
    h = __float2bfloat16(x);
    l = __float2bfloat16(x - __bfloat162float(h));
}

// ---------------- CSR build ----------------
__global__ void k_zero_deg() {
    int i = blockIdx.x * blockDim.x + threadIdx.x;
    if (i < NN) g_deg[i] = 0;
}
__global__ void k_count(const int* __restrict__ ei) {
    int e = blockIdx.x * blockDim.x + threadIdx.x;
    if (e < EE) atomicAdd(&g_deg[ei[EE + e]], 1);
}
__global__ void k_scan() {
    __shared__ int sums[1024];
    const int PER = 20;
    int tid = threadIdx.x;
    int base = tid * PER;
    int local[PER];
    int s = 0;
#pragma unroll
    for (int i = 0; i < PER; i++) {
        int idx = base + i;
        int d = (idx < NN) ? g_deg[idx] : 0;
        local[i] = s;
        s += d;
    }
    sums[tid] = s;
    __syncthreads();
    for (int off = 1; off < 1024; off <<= 1) {
        int t2 = (tid >= off) ? sums[tid - off] : 0;
        __syncthreads();
        sums[tid] += t2;
        __syncthreads();
    }
    int pre = (tid > 0) ? sums[tid - 1] : 0;
#pragma unroll
    for (int i = 0; i < PER; i++) {
        int idx = base + i;
        if (idx < NN) {
            g_rowptr[idx] = pre + local[i];
            g_cursor[idx] = 0;
        }
    }
    if (tid == 1023) g_rowptr[NN] = sums[1023];
}
__global__ void k_scatter(const int* __restrict__ ei) {
    int e = blockIdx.x * blockDim.x + threadIdx.x;
    if (e < EE) {
        int d = ei[EE + e];
        int pos = g_rowptr[d] + atomicAdd(&g_cursor[d], 1);
        g_edge[pos] = make_int2(e, ei[e]);
    }
}

// ---------------- edge attributes (fp32, zero pad to 96) ----------------
__global__ void k_edge_attr(const int* __restrict__ ei,
                            const float* __restrict__ last_update,
                            const float* __restrict__ t,
                            const float* __restrict__ msg,
                            const float* __restrict__ wlin,
                            const float* __restrict__ blin,
                            const float* __restrict__ w,
                            const float* __restrict__ b) {
    int idx = blockIdx.x * blockDim.x + threadIdx.x;
    if (idx >= EE * EK) return;
    int e = idx / EK;
    int j = idx - e * EK;
    float v;
    if (j < 9) {
        float rel = last_update[ei[e]] - t[e];
        if (j == 0) v = rel * wlin[0] + blin[0];
        else        v = sinf(rel * w[j - 1] + b[j - 1]);
    } else if (j < 73) {
        v = msg[e * 64 + (j - 9)];
    } else {
        v = 0.f;
    }
    g_ea[idx] = v;
}

// ---------------- weight packing ----------------
__global__ void k_split_wn(const float* __restrict__ Wq, const float* __restrict__ Wk,
                           const float* __restrict__ Wv, const float* __restrict__ Ws) {
    int idx = blockIdx.x * blockDim.x + threadIdx.x;
    if (idx >= 12 * 65536) return;
    int mat = idx >> 16;
    int r = idx & 65535;
    int n = r >> 8, k = r & 255;
    int layer = mat >> 2, ty = mat & 3;
    const float* W = (ty == 0 ? Wq : ty == 1 ? Wk : ty == 2 ? Wv : Ws) + layer * 65536;
    int dst = layer * 1280 * 256 + (ty * 256 + n) * 256 + k;
    splitbf(W[k * 256 + n], g_wn_hi[dst], g_wn_lo[dst]);
}
// composite Wc rows (1024..1279): Wc[k][c=h*128+j] = sum_m Wq[k][h*128+m]*We[j][h*128+m]
__global__ void k_wc(const float* __restrict__ Wq, const float* __restrict__ We) {
    int idx = blockIdx.x * blockDim.x + threadIdx.x;
    if (idx >= 3 * 65536) return;
    int layer = idx >> 16;
    int o = idx & 65535;
    int c = o >> 8, k = o & 255;
    int hh = c >> 7, j = c & 127;
    float s = 0.f;
    if (j < 73) {
        const float* wq = Wq + layer * 65536 + k * 256 + hh * 128;
        const float* we = We + layer * 73 * 256 + j * 256 + hh * 128;
#pragma unroll 8
        for (int m = 0; m < 128; m++) s += wq[m] * we[m];
    }
    int dst = layer * 1280 * 256 + (1024 + c) * 256 + k;
    splitbf(s, g_wn_hi[dst], g_wn_lo[dst]);
}
__global__ void k_bz(const float* __restrict__ bq, const float* __restrict__ We) {
    int idx = blockIdx.x * blockDim.x + threadIdx.x;
    if (idx >= 3 * 256) return;
    int layer = idx >> 8, c = idx & 255;
    int hh = c >> 7, j = c & 127;
    float s = 0.f;
    if (j < 73) {
        const float* bqp = bq + layer * 256 + hh * 128;
        const float* we = We + layer * 73 * 256 + j * 256 + hh * 128;
#pragma unroll 8
        for (int m = 0; m < 128; m++) s += bqp[m] * we[m];
    }
    g_bz[idx] = s;
}
__global__ void k_wef(const float* __restrict__ We) {
    int idx = blockIdx.x * blockDim.x + threadIdx.x;
    if (idx >= 3 * EK * 256) return;
    int l = idx / (EK * 256);
    int r = idx - l * (EK * 256);
    int d = r >> 8, c = r & 255;
    g_wef[idx] = (d < 73) ? We[l * 73 * 256 + d * 256 + c] : 0.f;
}
__global__ void k_split_wl(const float* __restrict__ lin_w) {
    int idx = blockIdx.x * blockDim.x + threadIdx.x;
    if (idx >= 32768) return;
    int n = idx >> 7, k = idx & 127;
    float v = (k < 100) ? lin_w[k * 256 + n] : 0.f;
    splitbf(v, g_wl_hi[idx], g_wl_lo[idx]);
}
__global__ void k_split_x(const float* __restrict__ x) {
    int idx = blockIdx.x * blockDim.x + threadIdx.x;
    if (idx >= NN * 128) return;
    int m = idx >> 7, k = idx & 127;
    float v = (k < 100) ? x[m * 100 + k] : 0.f;
    splitbf(v, g_x_hi[idx], g_x_lo[idx]);
}
__global__ void k_split_h() {
    int idx = blockIdx.x * blockDim.x + threadIdx.x;
    if (idx >= NN * 256) return;
    splitbf(g_h[idx], g_h_hi[idx], g_h_lo[idx]);
}

// ---------------- split-bf16 mma.sync GEMM (R12 config: K-tile 32, 2 CTAs/SM) ----------------
#define LDT 40                       // smem row stride in bf16 (80 B)
#define TILE_B (128 * LDT * 2)       // 10240 B per operand tile
#define STAGE_B (4 * TILE_B)
#define SMEM_MM (2 * STAGE_B)        // 81920 B

__device__ __forceinline__ void mma16816(float* d, const uint32_t* a, const uint32_t* b) {
    asm volatile(
        "mma.sync.aligned.m16n8k16.row.col.f32.bf16.bf16.f32 "
        "{%0,%1,%2,%3},{%4,%5,%6,%7},{%8,%9},{%0,%1,%2,%3};"
        : "+f"(d[0]), "+f"(d[1]), "+f"(d[2]), "+f"(d[3])
        : "r"(a[0]), "r"(a[1]), "r"(a[2]), "r"(a[3]), "r"(b[0]), "r"(b[1]));
}
__device__ __forceinline__ void ldm4(uint32_t* r, uint32_t addr) {
    asm volatile("ldmatrix.sync.aligned.m8n8.x4.shared.b16 {%0,%1,%2,%3}, [%4];"
                 : "=r"(r[0]), "=r"(r[1]), "=r"(r[2]), "=r"(r[3]) : "r"(addr));
}
__device__ __forceinline__ void cp16(uint32_t dst, const void* src, int szr) {
    asm volatile("cp.async.cg.shared.global [%0], [%1], 16, %2;"
                 :: "r"(dst), "l"(src), "r"(szr));
}

__device__ __forceinline__ void mm_load_stage(
    uint32_t sbase, int st, int kt, int row0, int col0, int M, int K,
    const __nv_bfloat16* Ah, const __nv_bfloat16* Al,
    const __nv_bfloat16* Bh, const __nv_bfloat16* Bl, int tid) {
    int kg0 = kt * 32;
#pragma unroll
    for (int i = 0; i < 8; i++) {
        int c = tid + i * 256;
        int op = c >> 9;                       // 0:Ah 1:Al 2:Bh 3:Bl
        int r = (c >> 2) & 127, seg = c & 3;
        const __nv_bfloat16* S = (op == 0) ? Ah : (op == 1) ? Al : (op == 2) ? Bh : Bl;
        int gr = (op < 2) ? (row0 + r) : (col0 + r);
        int valid = (op < 2) ? (gr < M) : 1;
        uint32_t dst = sbase + st * STAGE_B + op * TILE_B + r * (LDT * 2) + seg * 16;
        const __nv_bfloat16* src = S + (valid ? ((size_t)gr * K + kg0 + seg * 8) : 0);
        cp16(dst, src, valid ? 16 : 0);
    }
}

__global__ __launch_bounds__(256) void k_mma(
    const __nv_bfloat16* __restrict__ Ah, const __nv_bfloat16* __restrict__ Al,
    const __nv_bfloat16* __restrict__ Bh, const __nv_bfloat16* __restrict__ Bl,
    const float* b0, const float* b1, const float* b2, const float* b3, const float* b4,
    float* C0, float* C1, float* C2, float* C3, float* C4,
    int M, int K) {
    extern __shared__ char sm[];
    uint32_t sbase = smem_u32(sm);
    int tid = threadIdx.x, warp = tid >> 5, lane = tid & 31;
    int g = lane >> 2, tig = lane & 3;
    int wm = (warp & 1) * 64, wn = (warp >> 1) * 32;
    int row0 = blockIdx.y * 128, col0 = blockIdx.x * 128;
    int nkt = K >> 5;

    float acc[4][4][4];
#pragma unroll
    for (int mi = 0; mi < 4; mi++)
#pragma unroll
        for (int ni = 0; ni < 4; ni++)
#pragma unroll
            for (int r = 0; r < 4; r++) acc[mi][ni][r] = 0.f;

    mm_load_stage(sbase, 0, 0, row0, col0, M, K, Ah, Al, Bh, Bl, tid);
    asm volatile("cp.async.commit_group;");

    for (int kt = 0; kt < nkt; kt++) {
        if (kt + 1 < nkt) {
            mm_load_stage(sbase, (kt + 1) & 1, kt + 1, row0, col0, M, K, Ah, Al, Bh, Bl, tid);
            asm volatile("cp.async.commit_group;");
            asm volatile("cp.async.wait_group 1;");
        } else {
            asm volatile("cp.async.wait_group 0;");
        }
        __syncthreads();

        uint32_t at  = sbase + (kt & 1) * STAGE_B;
        uint32_t alt = at + TILE_B;
        uint32_t bt  = at + 2 * TILE_B;
        uint32_t blt = at + 3 * TILE_B;
        int arow = (lane & 15);
        int acol = (lane >> 4) * 8;
#pragma unroll
        for (int ks = 0; ks < 32; ks += 16) {
            uint32_t rah[4][4], ral[4][4], rbh[4][2], rbl[4][2];
#pragma unroll
            for (int mi = 0; mi < 4; mi++) {
                uint32_t off = ((wm + mi * 16 + arow) * LDT + ks + acol) * 2;
                ldm4(rah[mi], at + off);
                ldm4(ral[mi], alt + off);
            }
#pragma unroll
            for (int ni = 0; ni < 4; ni++) {
                uint32_t off = ((wn + ni * 8 + g) * LDT + ks + 2 * tig) * 2;
                rbh[ni][0] = *(const uint32_t*)(sm + (bt - sbase) + off);
                rbh[ni][1] = *(const uint32_t*)(sm + (bt - sbase) + off + 16);
                rbl[ni][0] = *(const uint32_t*)(sm + (blt - sbase) + off);
                rbl[ni][1] = *(const uint32_t*)(sm + (blt - sbase) + off + 16);
            }
#pragma unroll
            for (int mi = 0; mi < 4; mi++)
#pragma unroll
                for (int ni = 0; ni < 4; ni++) {
                    mma16816(acc[mi][ni], rah[mi], rbh[ni]);
                    mma16816(acc[mi][ni], rah[mi], rbl[ni]);
                    mma16816(acc[mi][ni], ral[mi], rbh[ni]);
                }
        }
        __syncthreads();
    }

    int cb = col0 >> 8;
    float* C = (cb == 0) ? C0 : (cb == 1) ? C1 : (cb == 2) ? C2 : (cb == 3) ? C3 : C4;
    const float* bias = (cb == 0) ? b0 : (cb == 1) ? b1 : (cb == 2) ? b2 : (cb == 3) ? b3 : b4;
    int coll0 = col0 & 255;
#pragma unroll
    for (int ni = 0; ni < 4; ni++) {
        int col = coll0 + wn + ni * 8 + 2 * tig;
        float2 bz = make_float2(0.f, 0.f);
        if (bias) bz = *(const float2*)(bias + col);
#pragma unroll
        for (int mi = 0; mi < 4; mi++) {
            int r = row0 + wm + mi * 16 + g;
            if (r < M) {
                float2 o = make_float2(acc[mi][ni][0] + bz.x, acc[mi][ni][1] + bz.y);
                *(float2*)(C + (size_t)r * 256 + col) = o;
            }
            if (r + 8 < M) {
                float2 o = make_float2(acc[mi][ni][2] + bz.x, acc[mi][ni][3] + bz.y);
                *(float2*)(C + (size_t)(r + 8) * 256 + col) = o;
            }
        }
    }
}

// ---------------- attention: warp per (node, head), unroll 2 (fp32 asum out) ----------------
__global__ void k_attn() {
    int gw = (blockIdx.x * blockDim.x + threadIdx.x) >> 5;
    int lane = threadIdx.x & 31;
    if (gw >= NN * HH) return;
    int n = gw >> 1, h = gw & 1;
    int hoff = h * CC + lane * 4;
    int base = n * DD + hoff;
    float4 q4 = *(const float4*)(g_q + base);
    bool eal = (lane < 24);
    float4 z4 = make_float4(0.f, 0.f, 0.f, 0.f);
    if (eal) z4 = *(const float4*)(g_z + base);
    int beg = g_rowptr[n], end = g_rowptr[n + 1];
    float m = -3.4e38f, l = 0.f;
    float ax = 0.f, ay = 0.f, az = 0.f, aw = 0.f;
    float sx = 0.f, sy = 0.f, sz = 0.f, sw = 0.f;
    const float scale = 0.0883883476483184406f;  // 1/sqrt(128)

    int i = beg;
    for (; i + 2 <= end; i += 2) {
        int2 ed0 = g_edge[i];
        int2 ed1 = g_edge[i + 1];
        float4 ea0 = make_float4(0.f, 0.f, 0.f, 0.f), ea1 = ea0;
        if (eal) {
            ea0 = *(const float4*)(g_ea + (size_t)ed0.x * EK + lane * 4);
            ea1 = *(const float4*)(g_ea + (size_t)ed1.x * EK + lane * 4);
        }
        const float4 k0 = *(const float4*)(g_k + (size_t)ed0.y * DD + hoff);
        const float4 v0 = *(const float4*)(g_v + (size_t)ed0.y * DD + hoff);
        const float4 k1 = *(const float4*)(g_k + (size_t)ed1.y * DD + hoff);
        const float4 v1 = *(const float4*)(g_v + (size_t)ed1.y * DD + hoff);
        float p0 = q4.x * k0.x + q4.y * k0.y + q4.z * k0.z + q4.w * k0.w +
                   z4.x * ea0.x + z4.y * ea0.y + z4.z * ea0.z + z4.w * ea0.w;
        float p1 = q4.x * k1.x + q4.y * k1.y + q4.z * k1.z + q4.w * k1.w +
                   z4.x * ea1.x + z4.y * ea1.y + z4.z * ea1.z + z4.w * ea1.w;
#pragma unroll
        for (int off = 16; off; off >>= 1) {
            p0 += __shfl_xor_sync(0xffffffffu, p0, off);
            p1 += __shfl_xor_sync(0xffffffffu, p1, off);
        }
        float a0 = p0 * scale, a1 = p1 * scale;
        float mnew = fmaxf(m, fmaxf(a0, a1));
        float corr = __expf(m - mnew);
        float w0 = __expf(a0 - mnew);
        float w1 = __expf(a1 - mnew);
        l = l * corr + w0 + w1;
        ax = ax * corr + w0 * v0.x + w1 * v1.x;
        ay = ay * corr + w0 * v0.y + w1 * v1.y;
        az = az * corr + w0 * v0.z + w1 * v1.z;
        aw = aw * corr + w0 * v0.w + w1 * v1.w;
        sx = sx * corr + w0 * ea0.x + w1 * ea1.x;
        sy = sy * corr + w0 * ea0.y + w1 * ea1.y;
        sz = sz * corr + w0 * ea0.z + w1 * ea1.z;
        sw = sw * corr + w0 * ea0.w + w1 * ea1.w;
        m = mnew;
    }
    for (; i < end; i++) {
        int2 ed = g_edge[i];
        float4 ea0 = make_float4(0.f, 0.f, 0.f, 0.f);
        if (eal) ea0 = *(const float4*)(g_ea + (size_t)ed.x * EK + lane * 4);
        const float4 k0 = *(const float4*)(g_k + (size_t)ed.y * DD + hoff);
        const float4 v0 = *(const float4*)(g_v + (size_t)ed.y * DD + hoff);
        float p0 = q4.x * k0.x + q4.y * k0.y + q4.z * k0.z + q4.w * k0.w +
                   z4.x * ea0.x + z4.y * ea0.y + z4.z * ea0.z + z4.w * ea0.w;
#pragma unroll
        for (int off = 16; off; off >>= 1)
            p0 += __shfl_xor_sync(0xffffffffu, p0, off);
        float a0 = p0 * scale;
        float mnew = fmaxf(m, a0);
        float corr = __expf(m - mnew);
        float w0 = __expf(a0 - mnew);
        l = l * corr + w0;
        ax = ax * corr + w0 * v0.x;
        ay = ay * corr + w0 * v0.y;
        az = az * corr + w0 * v0.z;
        aw = aw * corr + w0 * v0.w;
        sx = sx * corr + w0 * ea0.x;
        sy = sy * corr + w0 * ea0.y;
        sz = sz * corr + w0 * ea0.z;
        sw = sw * corr + w0 * ea0.w;
        m = mnew;
    }
    float inv = (l > 0.f) ? 1.f / l : 0.f;
    float4 o = {ax * inv, ay * inv, az * inv, aw * inv};
    *(float4*)(g_aggr + base) = o;
    if (eal) {
        float4 wv = make_float4(sx * inv, sy * inv, sz * inv, sw * inv);
        *(float4*)(g_asum + (size_t)(h * NN + n) * EK + lane * 4) = wv;
    }
}

// ---------------- residual + e-contribution + layernorm + silu (+ fused split) ----------------
__global__ void k_node_update(const float* __restrict__ ln_g,
                              const float* __restrict__ ln_b,
                              const float* __restrict__ wef,
                              float* __restrict__ out) {
    __shared__ float sas[2 * EK];
    __shared__ float red[8];
    int n = blockIdx.x, t = threadIdx.x;
    int idx = n * DD + t;
    if (t < EK)            sas[t] = g_asum[(size_t)n * EK + t];
    else if (t < 2 * EK)   sas[t] = g_asum[(size_t)(NN + n) * EK + (t - EK)];
    __syncthreads();

    // e-contribution for channel t: sum_d asum[head(t)][d] * We[d][t]
    const float* sp = sas + (t >> 7) * EK;
    const float* wcol = wef + t;
    float ag2 = 0.f;
#pragma unroll 8
    for (int d = 0; d < EK; d++) ag2 += sp[d] * wcol[d * 256];

    float y = g_h[idx] + g_aggr[idx] + ag2 + g_skip[idx];
    int w = t >> 5, lane = t & 31;

    float s = y;
#pragma unroll
    for (int off = 16; off; off >>= 1) s += __shfl_xor_sync(0xffffffffu, s, off);
    if (lane == 0) red[w] = s;
    __syncthreads();
    float mu = 0.f;
#pragma unroll
    for (int i = 0; i < 8; i++) mu += red[i];
    mu *= (1.f / DD);

    float d = y - mu;
    float s2 = d * d;
#pragma unroll
    for (int off = 16; off; off >>= 1) s2 += __shfl_xor_sync(0xffffffffu, s2, off);
    __syncthreads();
    if (lane == 0) red[w] = s2;
    __syncthreads();
    float var = 0.f;
#pragma unroll
    for (int i = 0; i < 8; i++) var += red[i];
    var *= (1.f / DD);

    float z = d * rsqrtf(var + 1e-5f) * ln_g[t] + ln_b[t];
    float y2 = z / (1.f + __expf(-z));
    out[idx] = y2;
    splitbf(y2, g_h_hi[idx], g_h_lo[idx]);
}

// ---------------- launch ----------------
extern "C" void kernel_launch(void* const* d_in, const int* in_sizes, int n_in,
                              void* d_out, int out_size) {
    const float* x    = (const float*)d_in[0];
    const float* lu   = (const float*)d_in[1];
    const int*   ei   = (const int*)d_in[2];
    const float* t    = (const float*)d_in[3];
    const float* msg  = (const float*)d_in[4];
    const float* wlin = (const float*)d_in[5];
    const float* blin = (const float*)d_in[6];
    const float* w    = (const float*)d_in[7];
    const float* b    = (const float*)d_in[8];
    const float* lin_w = (const float*)d_in[9];
    const float* lin_b = (const float*)d_in[10];
    const float* Wq = (const float*)d_in[11];
    const float* bq = (const float*)d_in[12];
    const float* Wk = (const float*)d_in[13];
    const float* bk = (const float*)d_in[14];
    const float* Wv = (const float*)d_in[15];
    const float* bv = (const float*)d_in[16];
    const float* We = (const float*)d_in[17];
    const float* Ws = (const float*)d_in[18];
    const float* bs = (const float*)d_in[19];
    const float* lng = (const float*)d_in[20];
    const float* lnb = (const float*)d_in[21];
    float* out = (float*)d_out;

    cudaFuncSetAttribute(k_mma, cudaFuncAttributeMaxDynamicSharedMemorySize, SMEM_MM);

    void* p;
    cudaGetSymbolAddress(&p, g_h);    float* ph = (float*)p;
    cudaGetSymbolAddress(&p, g_q);    float* pq = (float*)p;
    cudaGetSymbolAddress(&p, g_k);    float* pk = (float*)p;
    cudaGetSymbolAddress(&p, g_v);    float* pv = (float*)p;
    cudaGetSymbolAddress(&p, g_skip); float* ps = (float*)p;
    cudaGetSymbolAddress(&p, g_z);    float* pz = (float*)p;
    cudaGetSymbolAddress(&p, g_bz);   float* pbz = (float*)p;
    cudaGetSymbolAddress(&p, g_wef);  float* pwef = (float*)p;
    cudaGetSymbolAddress(&p, g_h_hi);  __nv_bfloat16* hhi = (__nv_bfloat16*)p;
    cudaGetSymbolAddress(&p, g_h_lo);  __nv_bfloat16* hlo = (__nv_bfloat16*)p;
    cudaGetSymbolAddress(&p, g_x_hi);  __nv_bfloat16* xhi = (__nv_bfloat16*)p;
    cudaGetSymbolAddress(&p, g_x_lo);  __nv_bfloat16* xlo = (__nv_bfloat16*)p;
    cudaGetSymbolAddress(&p, g_wn_hi); __nv_bfloat16* wnh = (__nv_bfloat16*)p;
    cudaGetSymbolAddress(&p, g_wn_lo); __nv_bfloat16* wnl = (__nv_bfloat16*)p;
    cudaGetSymbolAddress(&p, g_wl_hi); __nv_bfloat16* wlh = (__nv_bfloat16*)p;
    cudaGetSymbolAddress(&p, g_wl_lo); __nv_bfloat16* wll = (__nv_bfloat16*)p;

    // CSR build + edge attrs + weight packing + composite z-weights
    k_zero_deg<<<(NN + 255) / 256, 256>>>();
    k_count<<<(EE + 255) / 256, 256>>>(ei);
    k_scan<<<1, 1024>>>();
    k_scatter<<<(EE + 255) / 256, 256>>>(ei);
    k_edge_attr<<<(EE * EK + 255) / 256, 256>>>(ei, lu, t, msg, wlin, blin, w, b);
    k_split_wn<<<(12 * 65536 + 255) / 256, 256>>>(Wq, Wk, Wv, Ws);
    k_wc<<<(3 * 65536 + 255) / 256, 256>>>(Wq, We);
    k_bz<<<3, 256>>>(bq, We);
    k_wef<<<(3 * EK * 256 + 255) / 256, 256>>>(We);
    k_split_wl<<<(32768 + 255) / 256, 256>>>(lin_w);
    k_split_x<<<(NN * 128 + 255) / 256, 256>>>(x);

    dim3 gin(2, (NN + 127) / 128);
    dim3 gnode(10, (NN + 127) / 128);   // Q|K|V|S|Z fused, N=1280

    k_mma<<<gin, 256, SMEM_MM>>>(xhi, xlo, wlh, wll,
                                 lin_b, lin_b, lin_b, lin_b, lin_b,
                                 ph, ph, ph, ph, ph, NN, 128);
    k_split_h<<<(NN * 256 + 255) / 256, 256>>>();

    for (int i = 0; i < LL; i++) {
        k_mma<<<gnode, 256, SMEM_MM>>>(hhi, hlo,
                                       wnh + i * 1280 * 256, wnl + i * 1280 * 256,
                                       bq + i * DD, bk + i * DD, bv + i * DD, bs + i * DD,
                                       pbz + i * 256,
                                       pq, pk, pv, ps, pz, NN, 256);
        k_attn<<<(NN * HH * 32 + 255) / 256, 256>>>();
        k_node_update<<<NN, DD>>>(lng + i * DD, lnb + i * DD,
                                  pwef + i * EK * 256, (i == LL - 1) ? out : ph);
    }
}

// round 17
// speedup vs baseline: 1.1356x; 1.1110x over previous
#include <cuda_runtime.h>
#include <cuda_bf16.h>
#include <math.h>
#include <stdint.h>

#define NN 20000
#define EE 320000
#define DD 256
#define HH 2
#define CC 128
#define LL 3
#define EK 96      // edge-attr dim padded (real 73)
#define EK2 192    // two heads concatenated

// ---------------- scratch (static __device__, no allocation) ----------------
__device__ float g_ea[EE * EK];                    // fp32 edge attrs (123 MB)
__device__ __nv_bfloat16 g_h_hi[NN * 256];
__device__ __nv_bfloat16 g_h_lo[NN * 256];
__device__ __nv_bfloat16 g_x_hi[NN * 128];
__device__ __nv_bfloat16 g_x_lo[NN * 128];
__device__ __nv_bfloat16 g_wn_hi[3 * 1280 * 256];  // per layer rows: Wq|Wk|Wv|Ws|Wc (K-major)
__device__ __nv_bfloat16 g_wn_lo[3 * 1280 * 256];
__device__ __nv_bfloat16 g_we2_hi[3 * 256 * EK2];  // block We: row c, dims d (per-head windows)
__device__ __nv_bfloat16 g_we2_lo[3 * 256 * EK2];
__device__ __nv_bfloat16 g_wl_hi[256 * 128];
__device__ __nv_bfloat16 g_wl_lo[256 * 128];
__device__ __nv_bfloat16 g_as_hi[NN * EK2];        // asum [n][192]: h0 dims 0-95, h1 dims 96-191
__device__ __nv_bfloat16 g_as_lo[NN * EK2];
__device__ float g_bz[3 * 256];                    // bias of z block

__device__ float g_h[NN * DD];
__device__ float g_q[NN * DD];
__device__ float g_k[NN * DD];
__device__ float g_v[NN * DD];
__device__ float g_skip[NN * DD];
__device__ float g_z[NN * DD];                     // z = We^T q, per head 128-col block
__device__ float g_aggr[NN * DD];
__device__ float g_ag2[NN * DD];                   // e-contribution to aggregation
__device__ int   g_rowptr[NN + 1];
__device__ int   g_cursor[NN];
__device__ int   g_deg[NN];
__device__ int2  g_edge[EE];                       // (eid, src)

__device__ __forceinline__ uint32_t smem_u32(const void* p) {
    uint32_t a;
    asm("{ .reg .u64 t; cvta.to.shared.u64 t, %1; cvt.u32.u64 %0, t; }" : "=r"(a) : "l"(p));
    return a;
}
__device__ __forceinline__ void splitbf(float x, __nv_bfloat16& h, __nv_bfloat16& l) {
    h = __float2bfloat16(x);
    l = __float2bfloat16(x - __bfloat162float(h));
}

// ---------------- CSR build ----------------
__global__ void k_zero_deg() {
    int i = blockIdx.x * blockDim.x + threadIdx.x;
    if (i < NN) g_deg[i] = 0;
}
__global__ void k_count(const int* __restrict__ ei) {
    int e = blockIdx.x * blockDim.x + threadIdx.x;
    if (e < EE) atomicAdd(&g_deg[ei[EE + e]], 1);
}
__global__ void k_scan() {
    __shared__ int sums[1024];
    const int PER = 20;
    int tid = threadIdx.x;
    int base = tid * PER;
    int local[PER];
    int s = 0;
#pragma unroll
    for (int i = 0; i < PER; i++) {
        int idx = base + i;
        int d = (idx < NN) ? g_deg[idx] : 0;
        local[i] = s;
        s += d;
    }
    sums[tid] = s;
    __syncthreads();
    for (int off = 1; off < 1024; off <<= 1) {
        int t2 = (tid >= off) ? sums[tid - off] : 0;
        __syncthreads();
        sums[tid] += t2;
        __syncthreads();
    }
    int pre = (tid > 0) ? sums[tid - 1] : 0;
#pragma unroll
    for (int i = 0; i < PER; i++) {
        int idx = base + i;
        if (idx < NN) {
            g_rowptr[idx] = pre + local[i];
            g_cursor[idx] = 0;
        }
    }
    if (tid == 1023) g_rowptr[NN] = sums[1023];
}
__global__ void k_scatter(const int* __restrict__ ei) {
    int e = blockIdx.x * blockDim.x + threadIdx.x;
    if (e < EE) {
        int d = ei[EE + e];
        int pos = g_rowptr[d] + atomicAdd(&g_cursor[d], 1);
        g_edge[pos] = make_int2(e, ei[e]);
    }
}

// ---------------- edge attributes (fp32, zero pad to 96) ----------------
__global__ void k_edge_attr(const int* __restrict__ ei,
                            const float* __restrict__ last_update,
                            const float* __restrict__ t,
                            const float* __restrict__ msg,
                            const float* __restrict__ wlin,
                            const float* __restrict__ blin,
                            const float* __restrict__ w,
                            const float* __restrict__ b) {
    int idx = blockIdx.x * blockDim.x + threadIdx.x;
    if (idx >= EE * EK) return;
    int e = idx / EK;
    int j = idx - e * EK;
    float v;
    if (j < 9) {
        float rel = last_update[ei[e]] - t[e];
        if (j == 0) v = rel * wlin[0] + blin[0];
        else        v = sinf(rel * w[j - 1] + b[j - 1]);
    } else if (j < 73) {
        v = msg[e * 64 + (j - 9)];
    } else {
        v = 0.f;
    }
    g_ea[idx] = v;
}

// ---------------- weight packing ----------------
__global__ void k_split_wn(const float* __restrict__ Wq, const float* __restrict__ Wk,
                           const float* __restrict__ Wv, const float* __restrict__ Ws) {
    int idx = blockIdx.x * blockDim.x + threadIdx.x;
    if (idx >= 12 * 65536) return;
    int mat = idx >> 16;
    int r = idx & 65535;
    int n = r >> 8, k = r & 255;
    int layer = mat >> 2, ty = mat & 3;
    const float* W = (ty == 0 ? Wq : ty == 1 ? Wk : ty == 2 ? Wv : Ws) + layer * 65536;
    int dst = layer * 1280 * 256 + (ty * 256 + n) * 256 + k;
    splitbf(W[k * 256 + n], g_wn_hi[dst], g_wn_lo[dst]);
}
// composite Wc rows (1024..1279): Wc[k][c=h*128+j] = sum_m Wq[k][h*128+m]*We[j][h*128+m]
__global__ void k_wc(const float* __restrict__ Wq, const float* __restrict__ We) {
    int idx = blockIdx.x * blockDim.x + threadIdx.x;
    if (idx >= 3 * 65536) return;
    int layer = idx >> 16;
    int o = idx & 65535;
    int c = o >> 8, k = o & 255;
    int hh = c >> 7, j = c & 127;
    float s = 0.f;
    if (j < 73) {
        const float* wq = Wq + layer * 65536 + k * 256 + hh * 128;
        const float* we = We + layer * 73 * 256 + j * 256 + hh * 128;
#pragma unroll 8
        for (int m = 0; m < 128; m++) s += wq[m] * we[m];
    }
    int dst = layer * 1280 * 256 + (1024 + c) * 256 + k;
    splitbf(s, g_wn_hi[dst], g_wn_lo[dst]);
}
__global__ void k_bz(const float* __restrict__ bq, const float* __restrict__ We) {
    int idx = blockIdx.x * blockDim.x + threadIdx.x;
    if (idx >= 3 * 256) return;
    int layer = idx >> 8, c = idx & 255;
    int hh = c >> 7, j = c & 127;
    float s = 0.f;
    if (j < 73) {
        const float* bqp = bq + layer * 256 + hh * 128;
        const float* we = We + layer * 73 * 256 + j * 256 + hh * 128;
#pragma unroll 8
        for (int m = 0; m < 128; m++) s += bqp[m] * we[m];
    }
    g_bz[idx] = s;
}
// block-structured We2: row c (out channel), dim d in [0,192).
// c<128 (head0): val = We[d][c] for d<73, else 0.  c>=128 (head1): val = We[d-96][c] for d-96<73, else 0.
__global__ void k_we2(const float* __restrict__ We) {
    int idx = blockIdx.x * blockDim.x + threadIdx.x;
    if (idx >= 3 * 256 * EK2) return;
    int l = idx / (256 * EK2);
    int r = idx - l * (256 * EK2);
    int c = r / EK2, d = r - c * EK2;
    int hh = c >> 7;
    int dd = d - hh * EK;
    float v = 0.f;
    if (dd >= 0 && dd < 73) v = We[l * 73 * 256 + dd * 256 + c];
    splitbf(v, g_we2_hi[idx], g_we2_lo[idx]);
}
__global__ void k_split_wl(const float* __restrict__ lin_w) {
    int idx = blockIdx.x * blockDim.x + threadIdx.x;
    if (idx >= 32768) return;
    int n = idx >> 7, k = idx & 127;
    float v = (k < 100) ? lin_w[k * 256 + n] : 0.f;
    splitbf(v, g_wl_hi[idx], g_wl_lo[idx]);
}
__global__ void k_split_x(const float* __restrict__ x) {
    int idx = blockIdx.x * blockDim.x + threadIdx.x;
    if (idx >= NN * 128) return;
    int m = idx >> 7, k = idx & 127;
    float v = (k < 100) ? x[m * 100 + k] : 0.f;
    splitbf(v, g_x_hi[idx], g_x_lo[idx]);
}
__global__ void k_split_h() {
    int idx = blockIdx.x * blockDim.x + threadIdx.x;
    if (idx >= NN * 256) return;
    splitbf(g_h[idx], g_h_hi[idx], g_h_lo[idx]);
}

// ---------------- split-bf16 mma.sync GEMM (K-tile 32, forced 2 CTAs/SM) ----------------
#define LDT 40                       // smem row stride in bf16 (80 B)
#define TILE_B (128 * LDT * 2)       // 10240 B per operand tile
#define STAGE_B (4 * TILE_B)
#define SMEM_MM (2 * STAGE_B)        // 81920 B

__device__ __forceinline__ void mma16816(float* d, const uint32_t* a, const uint32_t* b) {
    asm volatile(
        "mma.sync.aligned.m16n8k16.row.col.f32.bf16.bf16.f32 "
        "{%0,%1,%2,%3},{%4,%5,%6,%7},{%8,%9},{%0,%1,%2,%3};"
        : "+f"(d[0]), "+f"(d[1]), "+f"(d[2]), "+f"(d[3])
        : "r"(a[0]), "r"(a[1]), "r"(a[2]), "r"(a[3]), "r"(b[0]), "r"(b[1]));
}
__device__ __forceinline__ void ldm4(uint32_t* r, uint32_t addr) {
    asm volatile("ldmatrix.sync.aligned.m8n8.x4.shared.b16 {%0,%1,%2,%3}, [%4];"
                 : "=r"(r[0]), "=r"(r[1]), "=r"(r[2]), "=r"(r[3]) : "r"(addr));
}
__device__ __forceinline__ void cp16(uint32_t dst, const void* src, int szr) {
    asm volatile("cp.async.cg.shared.global [%0], [%1], 16, %2;"
                 :: "r"(dst), "l"(src), "r"(szr));
}

__device__ __forceinline__ void mm_load_stage(
    uint32_t sbase, int st, int kt, int row0, int col0, int M, int K,
    const __nv_bfloat16* Ah, const __nv_bfloat16* Al,
    const __nv_bfloat16* Bh, const __nv_bfloat16* Bl, int tid) {
    int kg0 = kt * 32;
#pragma unroll
    for (int i = 0; i < 8; i++) {
        int c = tid + i * 256;
        int op = c >> 9;                       // 0:Ah 1:Al 2:Bh 3:Bl
        int r = (c >> 2) & 127, seg = c & 3;
        const __nv_bfloat16* S = (op == 0) ? Ah : (op == 1) ? Al : (op == 2) ? Bh : Bl;
        int gr = (op < 2) ? (row0 + r) : (col0 + r);
        int valid = (op < 2) ? (gr < M) : 1;
        uint32_t dst = sbase + st * STAGE_B + op * TILE_B + r * (LDT * 2) + seg * 16;
        const __nv_bfloat16* src = S + (valid ? ((size_t)gr * K + kg0 + seg * 8) : 0);
        cp16(dst, src, valid ? 16 : 0);
    }
}

__global__ __launch_bounds__(256, 2) void k_mma(
    const __nv_bfloat16* __restrict__ Ah, const __nv_bfloat16* __restrict__ Al,
    const __nv_bfloat16* __restrict__ Bh, const __nv_bfloat16* __restrict__ Bl,
    const float* b0, const float* b1, const float* b2, const float* b3, const float* b4,
    float* C0, float* C1, float* C2, float* C3, float* C4,
    int M, int K) {
    extern __shared__ char sm[];
    uint32_t sbase = smem_u32(sm);
    int tid = threadIdx.x, warp = tid >> 5, lane = tid & 31;
    int g = lane >> 2, tig = lane & 3;
    int wm = (warp & 1) * 64, wn = (warp >> 1) * 32;
    int row0 = blockIdx.y * 128, col0 = blockIdx.x * 128;
    int nkt = K >> 5;

    float acc[4][4][4];
#pragma unroll
    for (int mi = 0; mi < 4; mi++)
#pragma unroll
        for (int ni = 0; ni < 4; ni++)
#pragma unroll
            for (int r = 0; r < 4; r++) acc[mi][ni][r] = 0.f;

    mm_load_stage(sbase, 0, 0, row0, col0, M, K, Ah, Al, Bh, Bl, tid);
    asm volatile("cp.async.commit_group;");

    for (int kt = 0; kt < nkt; kt++) {
        if (kt + 1 < nkt) {
            mm_load_stage(sbase, (kt + 1) & 1, kt + 1, row0, col0, M, K, Ah, Al, Bh, Bl, tid);
            asm volatile("cp.async.commit_group;");
            asm volatile("cp.async.wait_group 1;");
        } else {
            asm volatile("cp.async.wait_group 0;");
        }
        __syncthreads();

        uint32_t at  = sbase + (kt & 1) * STAGE_B;
        uint32_t alt = at + TILE_B;
        uint32_t bt  = at + 2 * TILE_B;
        uint32_t blt = at + 3 * TILE_B;
        int arow = (lane & 15);
        int acol = (lane >> 4) * 8;
#pragma unroll
        for (int ks = 0; ks < 32; ks += 16) {
            uint32_t rah[4][4], ral[4][4], rbh[4][2], rbl[4][2];
#pragma unroll
            for (int mi = 0; mi < 4; mi++) {
                uint32_t off = ((wm + mi * 16 + arow) * LDT + ks + acol) * 2;
                ldm4(rah[mi], at + off);
                ldm4(ral[mi], alt + off);
            }
#pragma unroll
            for (int ni = 0; ni < 4; ni++) {
                uint32_t off = ((wn + ni * 8 + g) * LDT + ks + 2 * tig) * 2;
                rbh[ni][0] = *(const uint32_t*)(sm + (bt - sbase) + off);
                rbh[ni][1] = *(const uint32_t*)(sm + (bt - sbase) + off + 16);
                rbl[ni][0] = *(const uint32_t*)(sm + (blt - sbase) + off);
                rbl[ni][1] = *(const uint32_t*)(sm + (blt - sbase) + off + 16);
            }
#pragma unroll
            for (int mi = 0; mi < 4; mi++)
#pragma unroll
                for (int ni = 0; ni < 4; ni++) {
                    mma16816(acc[mi][ni], rah[mi], rbh[ni]);
                    mma16816(acc[mi][ni], rah[mi], rbl[ni]);
                    mma16816(acc[mi][ni], ral[mi], rbh[ni]);
                }
        }
        __syncthreads();
    }

    int cb = col0 >> 8;
    float* C = (cb == 0) ? C0 : (cb == 1) ? C1 : (cb == 2) ? C2 : (cb == 3) ? C3 : C4;
    const float* bias = (cb == 0) ? b0 : (cb == 1) ? b1 : (cb == 2) ? b2 : (cb == 3) ? b3 : b4;
    int coll0 = col0 & 255;
#pragma unroll
    for (int ni = 0; ni < 4; ni++) {
        int col = coll0 + wn + ni * 8 + 2 * tig;
        float2 bz = make_float2(0.f, 0.f);
        if (bias) bz = *(const float2*)(bias + col);
#pragma unroll
        for (int mi = 0; mi < 4; mi++) {
            int r = row0 + wm + mi * 16 + g;
            if (r < M) {
                float2 o = make_float2(acc[mi][ni][0] + bz.x, acc[mi][ni][1] + bz.y);
                *(float2*)(C + (size_t)r * 256 + col) = o;
            }
            if (r + 8 < M) {
                float2 o = make_float2(acc[mi][ni][2] + bz.x, acc[mi][ni][3] + bz.y);
                *(float2*)(C + (size_t)(r + 8) * 256 + col) = o;
            }
        }
    }
}

// ---------------- attention: warp per (node, head), unroll 2 (bf16 asum to [n][192]) ----------------
__global__ void k_attn() {
    int gw = (blockIdx.x * blockDim.x + threadIdx.x) >> 5;
    int lane = threadIdx.x & 31;
    if (gw >= NN * HH) return;
    int n = gw >> 1, h = gw & 1;
    int hoff = h * CC + lane * 4;
    int base = n * DD + hoff;
    float4 q4 = *(const float4*)(g_q + base);
    bool eal = (lane < 24);
    float4 z4 = make_float4(0.f, 0.f, 0.f, 0.f);
    if (eal) z4 = *(const float4*)(g_z + base);
    int beg = g_rowptr[n], end = g_rowptr[n + 1];
    float m = -3.4e38f, l = 0.f;
    float ax = 0.f, ay = 0.f, az = 0.f, aw = 0.f;
    float sx = 0.f, sy = 0.f, sz = 0.f, sw = 0.f;
    const float scale = 0.0883883476483184406f;  // 1/sqrt(128)

    int i = beg;
    for (; i + 2 <= end; i += 2) {
        int2 ed0 = g_edge[i];
        int2 ed1 = g_edge[i + 1];
        float4 ea0 = make_float4(0.f, 0.f, 0.f, 0.f), ea1 = ea0;
        if (eal) {
            ea0 = *(const float4*)(g_ea + (size_t)ed0.x * EK + lane * 4);
            ea1 = *(const float4*)(g_ea + (size_t)ed1.x * EK + lane * 4);
        }
        const float4 k0 = *(const float4*)(g_k + (size_t)ed0.y * DD + hoff);
        const float4 v0 = *(const float4*)(g_v + (size_t)ed0.y * DD + hoff);
        const float4 k1 = *(const float4*)(g_k + (size_t)ed1.y * DD + hoff);
        const float4 v1 = *(const float4*)(g_v + (size_t)ed1.y * DD + hoff);
        float p0 = q4.x * k0.x + q4.y * k0.y + q4.z * k0.z + q4.w * k0.w +
                   z4.x * ea0.x + z4.y * ea0.y + z4.z * ea0.z + z4.w * ea0.w;
        float p1 = q4.x * k1.x + q4.y * k1.y + q4.z * k1.z + q4.w * k1.w +
                   z4.x * ea1.x + z4.y * ea1.y + z4.z * ea1.z + z4.w * ea1.w;
#pragma unroll
        for (int off = 16; off; off >>= 1) {
            p0 += __shfl_xor_sync(0xffffffffu, p0, off);
            p1 += __shfl_xor_sync(0xffffffffu, p1, off);
        }
        float a0 = p0 * scale, a1 = p1 * scale;
        float mnew = fmaxf(m, fmaxf(a0, a1));
        float corr = __expf(m - mnew);
        float w0 = __expf(a0 - mnew);
        float w1 = __expf(a1 - mnew);
        l = l * corr + w0 + w1;
        ax = ax * corr + w0 * v0.x + w1 * v1.x;
        ay = ay * corr + w0 * v0.y + w1 * v1.y;
        az = az * corr + w0 * v0.z + w1 * v1.z;
        aw = aw * corr + w0 * v0.w + w1 * v1.w;
        sx = sx * corr + w0 * ea0.x + w1 * ea1.x;
        sy = sy * corr + w0 * ea0.y + w1 * ea1.y;
        sz = sz * corr + w0 * ea0.z + w1 * ea1.z;
        sw = sw * corr + w0 * ea0.w + w1 * ea1.w;
        m = mnew;
    }
    for (; i < end; i++) {
        int2 ed = g_edge[i];
        float4 ea0 = make_float4(0.f, 0.f, 0.f, 0.f);
        if (eal) ea0 = *(const float4*)(g_ea + (size_t)ed.x * EK + lane * 4);
        const float4 k0 = *(const float4*)(g_k + (size_t)ed.y * DD + hoff);
        const float4 v0 = *(const float4*)(g_v + (size_t)ed.y * DD + hoff);
        float p0 = q4.x * k0.x + q4.y * k0.y + q4.z * k0.z + q4.w * k0.w +
                   z4.x * ea0.x + z4.y * ea0.y + z4.z * ea0.z + z4.w * ea0.w;
#pragma unroll
        for (int off = 16; off; off >>= 1)
            p0 += __shfl_xor_sync(0xffffffffu, p0, off);
        float a0 = p0 * scale;
        float mnew = fmaxf(m, a0);
        float corr = __expf(m - mnew);
        float w0 = __expf(a0 - mnew);
        l = l * corr + w0;
        ax = ax * corr + w0 * v0.x;
        ay = ay * corr + w0 * v0.y;
        az = az * corr + w0 * v0.z;
        aw = aw * corr + w0 * v0.w;
        sx = sx * corr + w0 * ea0.x;
        sy = sy * corr + w0 * ea0.y;
        sz = sz * corr + w0 * ea0.z;
        sw = sw * corr + w0 * ea0.w;
        m = mnew;
    }
    float inv = (l > 0.f) ? 1.f / l : 0.f;
    float4 o = {ax * inv, ay * inv, az * inv, aw * inv};
    *(float4*)(g_aggr + base) = o;
    if (eal) {
        int ai = n * EK2 + h * EK + lane * 4;
        splitbf(sx * inv, g_as_hi[ai + 0], g_as_lo[ai + 0]);
        splitbf(sy * inv, g_as_hi[ai + 1], g_as_lo[ai + 1]);
        splitbf(sz * inv, g_as_hi[ai + 2], g_as_lo[ai + 2]);
        splitbf(sw * inv, g_as_hi[ai + 3], g_as_lo[ai + 3]);
    }
}

// ---------------- residual + layernorm + silu (+ fused bf16 split of new h) ----------------
__global__ void k_node_update(const float* __restrict__ ln_g,
                              const float* __restrict__ ln_b,
                              float* __restrict__ out) {
    int n = blockIdx.x, t = threadIdx.x;
    int idx = n * DD + t;
    float y = g_h[idx] + g_aggr[idx] + g_ag2[idx] + g_skip[idx];
    __shared__ float red[8];
    int w = t >> 5, lane = t & 31;

    float s = y;
#pragma unroll
    for (int off = 16; off; off >>= 1) s += __shfl_xor_sync(0xffffffffu, s, off);
    if (lane == 0) red[w] = s;
    __syncthreads();
    float mu = 0.f;
#pragma unroll
    for (int i = 0; i < 8; i++) mu += red[i];
    mu *= (1.f / DD);

    float d = y - mu;
    float s2 = d * d;
#pragma unroll
    for (int off = 16; off; off >>= 1) s2 += __shfl_xor_sync(0xffffffffu, s2, off);
    __syncthreads();
    if (lane == 0) red[w] = s2;
    __syncthreads();
    float var = 0.f;
#pragma unroll
    for (int i = 0; i < 8; i++) var += red[i];
    var *= (1.f / DD);

    float z = d * rsqrtf(var + 1e-5f) * ln_g[t] + ln_b[t];
    float y2 = z / (1.f + __expf(-z));
    out[idx] = y2;
    splitbf(y2, g_h_hi[idx], g_h_lo[idx]);
}

// ---------------- launch ----------------
extern "C" void kernel_launch(void* const* d_in, const int* in_sizes, int n_in,
                              void* d_out, int out_size) {
    const float* x    = (const float*)d_in[0];
    const float* lu   = (const float*)d_in[1];
    const int*   ei   = (const int*)d_in[2];
    const float* t    = (const float*)d_in[3];
    const float* msg  = (const float*)d_in[4];
    const float* wlin = (const float*)d_in[5];
    const float* blin = (const float*)d_in[6];
    const float* w    = (const float*)d_in[7];
    const float* b    = (const float*)d_in[8];
    const float* lin_w = (const float*)d_in[9];
    const float* lin_b = (const float*)d_in[10];
    const float* Wq = (const float*)d_in[11];
    const float* bq = (const float*)d_in[12];
    const float* Wk = (const float*)d_in[13];
    const float* bk = (const float*)d_in[14];
    const float* Wv = (const float*)d_in[15];
    const float* bv = (const float*)d_in[16];
    const float* We = (const float*)d_in[17];
    const float* Ws = (const float*)d_in[18];
    const float* bs = (const float*)d_in[19];
    const float* lng = (const float*)d_in[20];
    const float* lnb = (const float*)d_in[21];
    float* out = (float*)d_out;

    cudaFuncSetAttribute(k_mma, cudaFuncAttributeMaxDynamicSharedMemorySize, SMEM_MM);

    void* p;
    cudaGetSymbolAddress(&p, g_h);    float* ph = (float*)p;
    cudaGetSymbolAddress(&p, g_q);    float* pq = (float*)p;
    cudaGetSymbolAddress(&p, g_k);    float* pk = (float*)p;
    cudaGetSymbolAddress(&p, g_v);    float* pv = (float*)p;
    cudaGetSymbolAddress(&p, g_skip); float* ps = (float*)p;
    cudaGetSymbolAddress(&p, g_z);    float* pz = (float*)p;
    cudaGetSymbolAddress(&p, g_ag2);  float* pg2 = (float*)p;
    cudaGetSymbolAddress(&p, g_bz);   float* pbz = (float*)p;
    cudaGetSymbolAddress(&p, g_h_hi);  __nv_bfloat16* hhi = (__nv_bfloat16*)p;
    cudaGetSymbolAddress(&p, g_h_lo);  __nv_bfloat16* hlo = (__nv_bfloat16*)p;
    cudaGetSymbolAddress(&p, g_x_hi);  __nv_bfloat16* xhi = (__nv_bfloat16*)p;
    cudaGetSymbolAddress(&p, g_x_lo);  __nv_bfloat16* xlo = (__nv_bfloat16*)p;
    cudaGetSymbolAddress(&p, g_wn_hi); __nv_bfloat16* wnh = (__nv_bfloat16*)p;
    cudaGetSymbolAddress(&p, g_wn_lo); __nv_bfloat16* wnl = (__nv_bfloat16*)p;
    cudaGetSymbolAddress(&p, g_we2_hi); __nv_bfloat16* w2h = (__nv_bfloat16*)p;
    cudaGetSymbolAddress(&p, g_we2_lo); __nv_bfloat16* w2l = (__nv_bfloat16*)p;
    cudaGetSymbolAddress(&p, g_wl_hi); __nv_bfloat16* wlh = (__nv_bfloat16*)p;
    cudaGetSymbolAddress(&p, g_wl_lo); __nv_bfloat16* wll = (__nv_bfloat16*)p;
    cudaGetSymbolAddress(&p, g_as_hi); __nv_bfloat16* ash = (__nv_bfloat16*)p;
    cudaGetSymbolAddress(&p, g_as_lo); __nv_bfloat16* asl = (__nv_bfloat16*)p;

    // CSR build + edge attrs + weight packing + composite z-weights
    k_zero_deg<<<(NN + 255) / 256, 256>>>();
    k_count<<<(EE + 255) / 256, 256>>>(ei);
    k_scan<<<1, 1024>>>();
    k_scatter<<<(EE + 255) / 256, 256>>>(ei);
    k_edge_attr<<<(EE * EK + 255) / 256, 256>>>(ei, lu, t, msg, wlin, blin, w, b);
    k_split_wn<<<(12 * 65536 + 255) / 256, 256>>>(Wq, Wk, Wv, Ws);
    k_wc<<<(3 * 65536 + 255) / 256, 256>>>(Wq, We);
    k_bz<<<3, 256>>>(bq, We);
    k_we2<<<(3 * 256 * EK2 + 255) / 256, 256>>>(We);
    k_split_wl<<<(32768 + 255) / 256, 256>>>(lin_w);
    k_split_x<<<(NN * 128 + 255) / 256, 256>>>(x);

    dim3 gin(2, (NN + 127) / 128);
    dim3 gnode(10, (NN + 127) / 128);   // Q|K|V|S|Z fused, N=1280
    dim3 ges(2, (NN + 127) / 128);      // merged e-sum GEMM, N=256, K=192

    k_mma<<<gin, 256, SMEM_MM>>>(xhi, xlo, wlh, wll,
                                 lin_b, lin_b, lin_b, lin_b, lin_b,
                                 ph, ph, ph, ph, ph, NN, 128);
    k_split_h<<<(NN * 256 + 255) / 256, 256>>>();

    for (int i = 0; i < LL; i++) {
        k_mma<<<gnode, 256, SMEM_MM>>>(hhi, hlo,
                                       wnh + i * 1280 * 256, wnl + i * 1280 * 256,
                                       bq + i * DD, bk + i * DD, bv + i * DD, bs + i * DD,
                                       pbz + i * 256,
                                       pq, pk, pv, ps, pz, NN, 256);
        k_attn<<<(NN * HH * 32 + 255) / 256, 256>>>();
        // merged e-contribution: [NN,192] @ We2^T -> g_ag2 [NN,256] in one launch
        k_mma<<<ges, 256, SMEM_MM>>>(ash, asl,
                                     w2h + i * 256 * EK2, w2l + i * 256 * EK2,
                                     (const float*)nullptr, nullptr, nullptr, nullptr, nullptr,
                                     pg2, pg2, nullptr, nullptr, nullptr,
                                     NN, EK2);
        k_node_update<<<NN, DD>>>(lng + i * DD, lnb + i * DD, (i == LL - 1) ? out : ph);
    }
}